// round 2
// baseline (speedup 1.0000x reference)
#include <cuda_runtime.h>
#include <math_constants.h>

// Problem constants (from reference)
#define B_      256
#define N_      16
#define M_      128
#define V_      64
#define H_      256
#define K_      8
#define NP1_    17      // N + 1
#define KO_     136     // K * (N+1)
#define TYPES_  12
#define SPANS_  15
#define NCOMBO  (SPANS_ * TYPES_)   // 180

// Output layout: new_d [B,M,V] floats, then new_v [B,40,3,V] zeros
#define OUT_D_ELEMS ((size_t)B_ * M_ * V_)
#define OUT_V_PER_B (40 * 3 * V_)   // 7680 floats per batch

// Scratch: one logit vector per (span,type) combo. 180*136*4 = 97,920 B.
__device__ float g_logits[NCOMBO * KO_];

// ============================================================================
// Kernel 1: logits[(sp,tt)] = te[tt] . W_sem[sp,tt] + b_sem[sp,tt]
// grid = 180 combos, 544 threads = 136 outputs x 4 H-quadrants (64 h each).
// ============================================================================
__global__ __launch_bounds__(544, 1)
void logits_kernel(const float* __restrict__ te_table,   // [21,H]
                   const float* __restrict__ W_sem,      // [15,12,H,KO]
                   const float* __restrict__ b_sem)      // [15,12,KO]
{
    __shared__ float  s_te[H_];
    __shared__ double s_part[544];

    const int combo = blockIdx.x;          // = (sp-2)*12 + (tt-9)
    const int tidx  = combo % TYPES_;      // tt - 9
    const int tid   = threadIdx.x;

    if (tid < H_) s_te[tid] = te_table[(size_t)(9 + tidx) * H_ + tid];
    __syncthreads();

    const float* __restrict__ Wg = W_sem + (size_t)combo * H_ * KO_;

    const int o = tid % KO_;       // output column 0..135
    const int q = tid / KO_;       // H quadrant 0..3
    const float* wp = Wg + (size_t)(q * 64) * KO_ + o;
    const float* tp = s_te + q * 64;

    float a0 = 0.f, a1 = 0.f, a2 = 0.f, a3 = 0.f;
    float a4 = 0.f, a5 = 0.f, a6 = 0.f, a7 = 0.f;
    #pragma unroll
    for (int h = 0; h < 64; h += 8) {
        a0 = fmaf(tp[h + 0], wp[(size_t)(h + 0) * KO_], a0);
        a1 = fmaf(tp[h + 1], wp[(size_t)(h + 1) * KO_], a1);
        a2 = fmaf(tp[h + 2], wp[(size_t)(h + 2) * KO_], a2);
        a3 = fmaf(tp[h + 3], wp[(size_t)(h + 3) * KO_], a3);
        a4 = fmaf(tp[h + 4], wp[(size_t)(h + 4) * KO_], a4);
        a5 = fmaf(tp[h + 5], wp[(size_t)(h + 5) * KO_], a5);
        a6 = fmaf(tp[h + 6], wp[(size_t)(h + 6) * KO_], a6);
        a7 = fmaf(tp[h + 7], wp[(size_t)(h + 7) * KO_], a7);
    }
    s_part[tid] = (((double)a0 + (double)a1) + ((double)a2 + (double)a3))
                + (((double)a4 + (double)a5) + ((double)a6 + (double)a7));
    __syncthreads();

    if (tid < KO_) {
        double s = (s_part[tid] + s_part[tid + KO_])
                 + (s_part[tid + 2 * KO_] + s_part[tid + 3 * KO_]);
        g_logits[combo * KO_ + tid] = (float)s + b_sem[(size_t)combo * KO_ + tid];
    }
}

// ============================================================================
// Kernel 2: per-batch Gumbel argmax selection + template application.
// grid = 256, 512 threads. Single fused global->global pass per segment:
// copy all 128 rows speculatively while computing olen; later segments /
// zero-fill overwrite the excess (idx strictly increases -> exact semantics).
// ============================================================================
__global__ __launch_bounds__(512, 2)
void apply_kernel(const float* __restrict__ decodings,     // [B,N,M,V]
                  const int*   __restrict__ target_types,  // [B]
                  const int*   __restrict__ spans,         // [B]
                  const float* __restrict__ gumbel,        // [B,K,NP1]
                  float*       __restrict__ out)
{
    __shared__ int s_sel[K_];
    __shared__ int s_red[16];
    __shared__ int s_olen;

    const int b    = blockIdx.x;
    const int tid  = threadIdx.x;
    const int w    = tid >> 5;
    const int lane = tid & 31;
    const int tt   = target_types[b];
    const int sp   = spans[b];

    // ---- selection ----
    if (tt == 20) {
        if (tid < K_) s_sel[tid] = (tid == 0) ? 1 : 0;
    } else if (w < K_) {
        const int combo = (sp - 2) * TYPES_ + (tt - 9);
        int   n   = lane;
        float val = -CUDART_INF_F;
        if (n < NP1_ && n <= sp) {
            val = g_logits[combo * KO_ + w * NP1_ + n]
                + gumbel[((size_t)b * K_ + w) * NP1_ + n];
        }
        float bv = val;
        int   bn = n;
        #pragma unroll
        for (int off = 16; off; off >>= 1) {
            float ov = __shfl_down_sync(0xffffffffu, bv, off);
            int   on = __shfl_down_sync(0xffffffffu, bn, off);
            if (ov > bv || (ov == bv && on < bn)) { bv = ov; bn = on; }
        }
        if (lane == 0) s_sel[w] = bn;
    }
    __syncthreads();

    // ---- fused copy + olen, sequential over segments (usually 1 iteration) ----
    const int c4    = tid & 15;    // float4 column within row (V=64 -> 16 float4)
    const int rbase = tid >> 4;    // base row 0..31
    int idx = 0;

    for (int k = 0; k < K_; k++) {
        if (idx >= M_) break;
        const int n = s_sel[k];
        if (n == 0) continue;

        const float4* __restrict__ tile4 =
            (const float4*)(decodings + ((size_t)b * N_ + (size_t)(n - 1)) * (M_ * V_));
        float4* __restrict__ out4 =
            (float4*)(out + ((size_t)b * M_ + idx) * V_);

        // load all 4 float4 up front (MLP=4)
        float4 v[4];
        #pragma unroll
        for (int j = 0; j < 4; j++)
            v[j] = tile4[(rbase + 32 * j) * 16 + c4];

        int local = 0;
        #pragma unroll
        for (int j = 0; j < 4; j++) {
            const int row = rbase + 32 * j;
            if (idx + row < M_)
                out4[row * 16 + c4] = v[j];
            // row is non-pad iff max over v>0 of d[row][v] > d[row][0]
            float m = (c4 == 0) ? fmaxf(fmaxf(v[j].y, v[j].z), v[j].w)
                                : fmaxf(fmaxf(v[j].x, v[j].y), fmaxf(v[j].z, v[j].w));
            #pragma unroll
            for (int off = 1; off < 16; off <<= 1)
                m = fmaxf(m, __shfl_xor_sync(0xffffffffu, m, off));
            const float d0 = __shfl_sync(0xffffffffu, v[j].x, lane & 16);
            if (m > d0) local = row + 1;
        }
        #pragma unroll
        for (int off = 16; off; off >>= 1)
            local = max(local, __shfl_down_sync(0xffffffffu, local, off));
        if (lane == 0) s_red[w] = local;
        __syncthreads();
        if (tid == 0) {
            int o = 0;
            #pragma unroll
            for (int i = 0; i < 16; i++) o = max(o, s_red[i]);
            s_olen = o;
        }
        __syncthreads();
        idx += min(s_olen, M_ - idx);
    }

    // ---- zero fill: tail of new_d, all of new_v ----
    const float4 z = make_float4(0.f, 0.f, 0.f, 0.f);
    {
        float* __restrict__ dst = out + ((size_t)b * M_ + idx) * V_;
        const int rem4 = (M_ - idx) * (V_ / 4);
        for (int i = tid; i < rem4; i += 512)
            ((float4*)dst)[i] = z;
    }
    {
        float* __restrict__ dv = out + OUT_D_ELEMS + (size_t)b * OUT_V_PER_B;
        #pragma unroll
        for (int i = tid; i < OUT_V_PER_B / 4; i += 512)
            ((float4*)dv)[i] = z;
    }
}

extern "C" void kernel_launch(void* const* d_in, const int* in_sizes, int n_in,
                              void* d_out, int out_size)
{
    (void)in_sizes; (void)n_in; (void)out_size;
    const float* decodings    = (const float*)d_in[0];
    // d_in[1] = variables : unused (new_v is all zeros)
    const int*   target_types = (const int*)d_in[2];
    const int*   spans        = (const int*)d_in[3];
    const float* te_table     = (const float*)d_in[4];
    const float* W_sem        = (const float*)d_in[5];
    const float* b_sem        = (const float*)d_in[6];
    const float* gumbel       = (const float*)d_in[7];
    float*       out          = (float*)d_out;

    logits_kernel<<<NCOMBO, 544>>>(te_table, W_sem, b_sem);
    apply_kernel<<<B_, 512>>>(decodings, target_types, spans, gumbel, out);
}